// round 9
// baseline (speedup 1.0000x reference)
#include <cuda_runtime.h>

#define HIDDEN    2048
#define NUM_HEADS 16
#define HEAD_DIM  128
#define BLK_SZ    64
#define NUM_SEQS  64
#define MAX_BLK   32
#define KS        32
#define NSPLIT    4
#define CHUNK     512
#define ATTN_SCALE 0.08838834764831845f   // 128^-0.5

// scratch (allocation-free __device__ globals), 16B-aligned for float4 access
__device__ __align__(16) float g_q[NUM_SEQS * HIDDEN];
__device__ __align__(16) float g_attn[NUM_SEQS * HIDDEN];
__device__ __align__(16) float g_part[KS * NUM_SEQS * HIDDEN];   // 16.8 MB
// flash-decode partials
__device__ __align__(16) float g_po[NUM_SEQS * NUM_HEADS * NSPLIT * HEAD_DIM];
__device__ float g_pm[NUM_SEQS * NUM_HEADS * NSPLIT];
__device__ float g_pl[NUM_SEQS * NUM_HEADS * NSPLIT];

// packed fp32x2 ops (sm_100+; ptxas never auto-fuses these)
#define PACK2(d, s)   asm("mov.b64 %0, {%1, %1};" : "=l"(d) : "f"(s))
#define FMA2(d, a, b) asm("fma.rn.f32x2 %0, %1, %2, %3;" : "=l"(d) : "l"(a), "l"(b), "l"(d))
#define UNPK2(lo, hi, v) asm("mov.b64 {%0, %1}, %2;" : "=f"(lo), "=f"(hi) : "l"(v))

// ---------------------------------------------------------------------------
// Split-K GEMM, f32x2 packed-FMA edition.
// C_part[z] = A[64, z*64:(z+1)*64] * B[..., n0:n0+128]
// BM=64, BN=128, BK=16, 4 k-tiles/CTA, 128 threads, 8x8 micro-tile (as 8x4 f32x2).
// grid = (16, 1, 32) = 512 CTAs.
// ---------------------------------------------------------------------------
__global__ __launch_bounds__(128)
void gemm_part(const float* __restrict__ A, const float* __restrict__ B,
               float* __restrict__ C, int ldb) {
    __shared__ __align__(16) float As[2][16 * 68];    // [k][m] padded
    __shared__ __align__(16) float Bs[2][16 * 128];   // [k][n]

    const int tid = threadIdx.x;
    const int tm  = tid >> 4;         // 0..7  (8 rows each)
    const int tn  = tid & 15;         // 0..15 (8 cols each)
    const int n0  = blockIdx.x * 128;
    const int z   = blockIdx.z;
    const int kbase = z * 64;

    // load mappings
    const int am  = tid >> 1;         // A row 0..63
    const int akq = (tid & 1) * 8;    // A k-offset {0,8}
    const int bk  = tid >> 3;         // B k-row 0..15
    const int bnq = (tid & 7) * 16;   // B n-offset (16 floats)

    // prologue: stage 0
    {
        const float* Ap = A + (size_t)am * HIDDEN + kbase + akq;
        float4 a0 = *(const float4*)(Ap);
        float4 a1 = *(const float4*)(Ap + 4);
        As[0][(akq + 0) * 68 + am] = a0.x;
        As[0][(akq + 1) * 68 + am] = a0.y;
        As[0][(akq + 2) * 68 + am] = a0.z;
        As[0][(akq + 3) * 68 + am] = a0.w;
        As[0][(akq + 4) * 68 + am] = a1.x;
        As[0][(akq + 5) * 68 + am] = a1.y;
        As[0][(akq + 6) * 68 + am] = a1.z;
        As[0][(akq + 7) * 68 + am] = a1.w;
        const float* Bp = B + (size_t)(kbase + bk) * ldb + n0 + bnq;
#pragma unroll
        for (int j = 0; j < 4; ++j)
            *(float4*)(&Bs[0][bk * 128 + bnq + 4 * j]) = *(const float4*)(Bp + 4 * j);
    }
    __syncthreads();

    unsigned long long acc[8][4];
#pragma unroll
    for (int i = 0; i < 8; ++i)
#pragma unroll
        for (int j = 0; j < 4; ++j) acc[i][j] = 0ULL;

#pragma unroll
    for (int it = 0; it < 4; ++it) {
        const int cur = it & 1;
        float4 a0n, a1n, bn[4];
        if (it < 3) {
            const int k0 = kbase + (it + 1) * 16;
            const float* Ap = A + (size_t)am * HIDDEN + k0 + akq;
            a0n = *(const float4*)(Ap);
            a1n = *(const float4*)(Ap + 4);
            const float* Bp = B + (size_t)(k0 + bk) * ldb + n0 + bnq;
#pragma unroll
            for (int j = 0; j < 4; ++j) bn[j] = *(const float4*)(Bp + 4 * j);
        }

#pragma unroll
        for (int kk = 0; kk < 16; ++kk) {
            float4 av0 = *(const float4*)(&As[cur][kk * 68 + tm * 8]);
            float4 av1 = *(const float4*)(&As[cur][kk * 68 + tm * 8 + 4]);
            ulonglong2 b01 = *(const ulonglong2*)(&Bs[cur][kk * 128 + tn * 8]);
            ulonglong2 b23 = *(const ulonglong2*)(&Bs[cur][kk * 128 + tn * 8 + 4]);
            float a_[8] = {av0.x, av0.y, av0.z, av0.w, av1.x, av1.y, av1.z, av1.w};
#pragma unroll
            for (int i = 0; i < 8; ++i) {
                unsigned long long ap;
                PACK2(ap, a_[i]);
                FMA2(acc[i][0], ap, b01.x);
                FMA2(acc[i][1], ap, b01.y);
                FMA2(acc[i][2], ap, b23.x);
                FMA2(acc[i][3], ap, b23.y);
            }
        }

        if (it < 3) {
            const int nxt = 1 - cur;
            As[nxt][(akq + 0) * 68 + am] = a0n.x;
            As[nxt][(akq + 1) * 68 + am] = a0n.y;
            As[nxt][(akq + 2) * 68 + am] = a0n.z;
            As[nxt][(akq + 3) * 68 + am] = a0n.w;
            As[nxt][(akq + 4) * 68 + am] = a1n.x;
            As[nxt][(akq + 5) * 68 + am] = a1n.y;
            As[nxt][(akq + 6) * 68 + am] = a1n.z;
            As[nxt][(akq + 7) * 68 + am] = a1n.w;
#pragma unroll
            for (int j = 0; j < 4; ++j)
                *(float4*)(&Bs[nxt][bk * 128 + bnq + 4 * j]) = bn[j];
        }
        __syncthreads();
    }

    // epilogue: unpack + store
#pragma unroll
    for (int i = 0; i < 8; ++i) {
        float r[8];
#pragma unroll
        for (int j = 0; j < 4; ++j) UNPK2(r[2 * j], r[2 * j + 1], acc[i][j]);
        float* Cp = C + ((size_t)z * 64 + tm * 8 + i) * HIDDEN + n0 + tn * 8;
        *(float4*)(Cp)     = make_float4(r[0], r[1], r[2], r[3]);
        *(float4*)(Cp + 4) = make_float4(r[4], r[5], r[6], r[7]);
    }
}

// out[i] = sum_z part[z][i] + bias[i % 2048]  (float4)
__global__ void reduce_bias(const float* __restrict__ part,
                            const float* __restrict__ bias,
                            float* __restrict__ out) {
    const int i = blockIdx.x * blockDim.x + threadIdx.x;
    const float4* p = (const float4*)part;
    float4 r = ((const float4*)bias)[i & 511];
#pragma unroll
    for (int zz = 0; zz < KS; ++zz) {
        float4 a = p[i + zz * 32768];
        r.x += a.x; r.y += a.y; r.z += a.z; r.w += a.w;
    }
    ((float4*)out)[i] = r;
}

// ---------------------------------------------------------------------------
// Flash-decode split attention (unchanged from R7).
// grid = (64 seqs, 16 heads, 4 chunks), 256 threads.
// ---------------------------------------------------------------------------
__global__ void attn_split(const float* __restrict__ kv,
                           const int* __restrict__ bt,
                           const int* __restrict__ seq_lens) {
    const int s = blockIdx.x, h = blockIdx.y, z = blockIdx.z;
    const int sl = seq_lens[s];
    const int start = z * CHUNK;
    if (start >= sl) return;
    const int clen = min(sl - start, CHUNK);

    const int tid = threadIdx.x;
    const int w  = tid >> 5;
    const int l  = tid & 31;
    const int q4 = l & 3;
    const int qd = l >> 2;

    __shared__ __align__(16) float qs[HEAD_DIM];
    __shared__ __align__(16) float vacc[8][HEAD_DIM];
    __shared__ float sc[CHUNK];
    __shared__ int   bts[8];
    __shared__ float red[8];
    __shared__ float bcast[2];

    if (tid < HEAD_DIM) qs[tid] = g_q[(size_t)s * HIDDEN + h * HEAD_DIM + tid];
    const int nblk = (clen + 63) >> 6;
    if (tid < nblk) bts[tid] = bt[s * MAX_BLK + z * 8 + tid];
    __syncthreads();

    float4 qreg[8];
#pragma unroll
    for (int c = 0; c < 8; ++c) qreg[c] = *(const float4*)(qs + c * 16 + q4 * 4);

    const int tok_in_blk = w * 8 + qd;
    const float* kbase = kv + (size_t)h * HEAD_DIM;

    // pass 1: scores
    for (int blk = 0; blk < nblk; ++blk) {
        const int phys = bts[blk];
        const int tl = blk * 64 + tok_in_blk;
        const float* kp = kbase + ((size_t)phys * BLK_SZ + tok_in_blk) * (size_t)HIDDEN;
        float d = 0.f;
#pragma unroll
        for (int c = 0; c < 8; ++c) {
            float4 kf = *(const float4*)(kp + c * 16 + q4 * 4);
            d += qreg[c].x * kf.x + qreg[c].y * kf.y + qreg[c].z * kf.z + qreg[c].w * kf.w;
        }
        d += __shfl_xor_sync(0xffffffffu, d, 1);
        d += __shfl_xor_sync(0xffffffffu, d, 2);
        if (q4 == 0 && tl < clen) sc[tl] = d * ATTN_SCALE;
    }
    __syncthreads();

    // chunk max
    float m = -3.4e38f;
    for (int t = tid; t < clen; t += 256) m = fmaxf(m, sc[t]);
#pragma unroll
    for (int o = 16; o; o >>= 1) m = fmaxf(m, __shfl_xor_sync(0xffffffffu, m, o));
    if (l == 0) red[w] = m;
    __syncthreads();
    if (tid == 0) {
        float mm = red[0];
#pragma unroll
        for (int i = 1; i < 8; ++i) mm = fmaxf(mm, red[i]);
        bcast[0] = mm;
    }
    __syncthreads();
    const float maxv = bcast[0];

    // exp + sum
    float ssum = 0.f;
    for (int t = tid; t < clen; t += 256) {
        float e = __expf(sc[t] - maxv);
        sc[t] = e;
        ssum += e;
    }
#pragma unroll
    for (int o = 16; o; o >>= 1) ssum += __shfl_xor_sync(0xffffffffu, ssum, o);
    if (l == 0) red[w] = ssum;
    __syncthreads();
    if (tid == 0) {
        float t2 = 0.f;
#pragma unroll
        for (int i = 0; i < 8; ++i) t2 += red[i];
        bcast[1] = t2;
    }

    // pass 2: weighted V (unnormalized)
    const float* vbase = kv + (size_t)2048 * 64 * 16 * 128 + (size_t)h * HEAD_DIM;
    float4 acc[8];
#pragma unroll
    for (int c = 0; c < 8; ++c) acc[c] = make_float4(0.f, 0.f, 0.f, 0.f);

    for (int blk = 0; blk < nblk; ++blk) {
        const int phys = bts[blk];
        const int tl = blk * 64 + tok_in_blk;
        const float wt = (tl < clen) ? sc[tl] : 0.f;
        const float* vp = vbase + ((size_t)phys * BLK_SZ + tok_in_blk) * (size_t)HIDDEN;
#pragma unroll
        for (int c = 0; c < 8; ++c) {
            float4 vf = *(const float4*)(vp + c * 16 + q4 * 4);
            acc[c].x += wt * vf.x;
            acc[c].y += wt * vf.y;
            acc[c].z += wt * vf.z;
            acc[c].w += wt * vf.w;
        }
    }

#pragma unroll
    for (int off = 4; off <= 16; off <<= 1) {
#pragma unroll
        for (int c = 0; c < 8; ++c) {
            acc[c].x += __shfl_xor_sync(0xffffffffu, acc[c].x, off);
            acc[c].y += __shfl_xor_sync(0xffffffffu, acc[c].y, off);
            acc[c].z += __shfl_xor_sync(0xffffffffu, acc[c].z, off);
            acc[c].w += __shfl_xor_sync(0xffffffffu, acc[c].w, off);
        }
    }
    if (qd == 0) {
#pragma unroll
        for (int c = 0; c < 8; ++c)
            *(float4*)(&vacc[w][c * 16 + q4 * 4]) = acc[c];
    }
    __syncthreads();

    const int pidx = (s * NUM_HEADS + h) * NSPLIT + z;
    if (tid < HEAD_DIM) {
        float r = 0.f;
#pragma unroll
        for (int ww = 0; ww < 8; ++ww) r += vacc[ww][tid];
        g_po[(size_t)pidx * HEAD_DIM + tid] = r;
    }
    if (tid == 0) { g_pm[pidx] = maxv; g_pl[pidx] = bcast[1]; }
}

// combine partials: grid (64,16), 128 threads
__global__ void attn_combine(const int* __restrict__ seq_lens) {
    const int s = blockIdx.x, h = blockIdx.y;
    const int d = threadIdx.x;
    const int sl = seq_lens[s];
    const int nch = (sl + CHUNK - 1) / CHUNK;
    const int pbase = (s * NUM_HEADS + h) * NSPLIT;

    float M = -3.4e38f;
    for (int zz = 0; zz < nch; ++zz) M = fmaxf(M, g_pm[pbase + zz]);
    float L = 0.f, o = 0.f;
    for (int zz = 0; zz < nch; ++zz) {
        const float f = __expf(g_pm[pbase + zz] - M);
        L += g_pl[pbase + zz] * f;
        o += g_po[(size_t)(pbase + zz) * HEAD_DIM + d] * f;
    }
    g_attn[(size_t)s * HIDDEN + h * HEAD_DIM + d] = o / L;
}

// ---------------------------------------------------------------------------
extern "C" void kernel_launch(void* const* d_in, const int* in_sizes, int n_in,
                              void* d_out, int out_size) {
    const float* hs     = (const float*)d_in[0];
    const float* kv     = (const float*)d_in[1];
    const float* W_attn = (const float*)d_in[2];
    const float* b_attn = (const float*)d_in[3];
    const float* W_proj = (const float*)d_in[4];
    const float* b_proj = (const float*)d_in[5];
    const int*   bt     = (const int*)d_in[6];
    const int*   sl     = (const int*)d_in[7];
    float* out = (float*)d_out;

    float *q_ptr, *attn_ptr, *part_ptr;
    cudaGetSymbolAddress((void**)&q_ptr,    g_q);
    cudaGetSymbolAddress((void**)&attn_ptr, g_attn);
    cudaGetSymbolAddress((void**)&part_ptr, g_part);

    // Q projection only: reference never uses K/V columns of W_attn.
    gemm_part<<<dim3(16, 1, KS), 128>>>(hs, W_attn, part_ptr, 3 * HIDDEN);
    reduce_bias<<<128, 256>>>(part_ptr, b_attn, q_ptr);

    attn_split<<<dim3(NUM_SEQS, NUM_HEADS, NSPLIT), 256>>>(kv, bt, sl);
    attn_combine<<<dim3(NUM_SEQS, NUM_HEADS), 128>>>(sl);

    gemm_part<<<dim3(16, 1, KS), 128>>>(attn_ptr, W_proj, part_ptr, HIDDEN);
    reduce_bias<<<128, 256>>>(part_ptr, b_proj, out);
}